// round 2
// baseline (speedup 1.0000x reference)
#include <cuda_runtime.h>

// Problem constants
#define NN      512      // x / columns of A
#define MM      512      // b / rows of A
#define NB      16       // columns per SMEM block
#define NBLK    (NN / NB)      // 32
#define STRIDE  20       // padded row stride (floats): 16B-aligned
#define TPB     512
#define C_ALPHA 0.005f
#define C_SCALE 0.001f
#define C_DELTA 0.1f
#define MAX_UPD 51       // MAX_ITER + 1 possible updates

__device__ __forceinline__ void cp_async16(float* dst_smem, const float* src_gmem) {
    unsigned d = (unsigned)__cvta_generic_to_shared(dst_smem);
    asm volatile("cp.async.cg.shared.global [%0], [%1], 16;" :: "r"(d), "l"(src_gmem));
}
__device__ __forceinline__ void cp_commit() { asm volatile("cp.async.commit_group;"); }
__device__ __forceinline__ void cp_wait0()  { asm volatile("cp.async.wait_group 0;"); }
__device__ __forceinline__ void cp_wait1()  { asm volatile("cp.async.wait_group 1;"); }

extern __shared__ float smem[];

// Load column block j (512 rows x 16 cols) of A into sA (stride 20) and commit a group.
__device__ __forceinline__ void load_block(float* sA, const float* __restrict__ Ap,
                                           int j, int tid) {
#pragma unroll
    for (int i = 0; i < 4; i++) {
        int lin = i * TPB + tid;      // 0..2047
        int r = lin >> 2;             // row 0..511
        int s = lin & 3;              // float4 segment 0..3
        cp_async16(sA + r * STRIDE + s * 4,
                   Ap + (size_t)r * NN + j * NB + s * 4);
    }
    cp_commit();
}

__global__ __launch_bounds__(TPB, 2)
void lva_kernel(const float* __restrict__ xin,
                const float* __restrict__ Ain,
                const float* __restrict__ bin,
                float* __restrict__ xout) {
    const int p   = blockIdx.x;
    const int tid = threadIdx.x;

    float* sA0   = smem;                    // 512*20 floats
    float* sA1   = sA0 + NN * STRIDE;       // 512*20 floats
    float* sx    = sA1 + NN * STRIDE;       // 512
    float* sy    = sx + NN;                 // 512
    float* sviol = sy + MM;                 // 512
    float* sb    = sviol + MM;              // 512
    float* spart = sb + MM;                 // 512 (g partials [32][16])
    float* sred  = spart + TPB;             // 32

    const float* Ap = Ain + (size_t)p * (MM * NN);

    sx[tid] = xin[p * NN + tid];
    sb[tid] = bin[p * MM + tid];
    sy[tid] = 0.0f;
    __syncthreads();

    // ---------- initial sweep: y = A @ x (double-buffered) ----------
    load_block(sA0, Ap, 0, tid);
    load_block(sA1, Ap, 1, tid);
    for (int j = 0; j < NBLK; j++) {
        if (j == NBLK - 1) cp_wait0(); else cp_wait1();
        __syncthreads();
        float* sA = (j & 1) ? sA1 : sA0;

        float acc = 0.0f;
        const float4* row = (const float4*)(sA + tid * STRIDE);
#pragma unroll
        for (int s = 0; s < 4; s++) {
            float4 a = row[s];
            int c = j * NB + s * 4;
            acc = fmaf(a.x, sx[c + 0], acc);
            acc = fmaf(a.y, sx[c + 1], acc);
            acc = fmaf(a.z, sx[c + 2], acc);
            acc = fmaf(a.w, sx[c + 3], acc);
        }
        sy[tid] += acc;
        __syncthreads();   // this buffer is free
        if (j + 2 < NBLK) load_block(sA, Ap, j + 2, tid);
    }

    // speculatively prefetch blocks 0,1 for the first iterate sweep
    load_block(sA0, Ap, 0, tid);
    load_block(sA1, Ap, 1, tid);

    // ---------- finalize: viol, total ----------
    float v = fmaxf(__fadd_rn(sy[tid], -sb[tid]), 0.0f);
    sviol[tid] = v;
#pragma unroll
    for (int o = 16; o > 0; o >>= 1) v += __shfl_down_sync(0xffffffffu, v, o);
    if ((tid & 31) == 0) sred[tid >> 5] = v;
    __syncthreads();
    if (tid < 32) {
        float w = (tid < 16) ? sred[tid] : 0.0f;
#pragma unroll
        for (int o = 8; o > 0; o >>= 1) w += __shfl_down_sync(0xffffffffu, w, o);
        if (tid == 0) sred[16] = w;
    }
    __syncthreads();
    float total = sred[16];

    // ---------- iterate: fused (g + x-update + next Ax), double-buffered ----------
    int it = 0;
    while (it < MAX_UPD && total >= C_DELTA) {
        sy[tid] = 0.0f;   // owner-thread only, no barrier needed

        for (int j = 0; j < NBLK; j++) {
            if (j == NBLK - 1) cp_wait0(); else cp_wait1();
            __syncthreads();
            float* sA = (j & 1) ? sA1 : sA0;

            // g pass: g_c = sum_m viol[m] * A[m, j*16+c]
            {
                int c = tid & 15, k = tid >> 4;          // k: 32 chunks of 16 rows
                const float* bp = sA + (k * 16) * STRIDE + c;
                const float* vp = sviol + k * 16;
                float g = 0.0f;
#pragma unroll
                for (int m = 0; m < 16; m++)
                    g = fmaf(vp[m], bp[m * STRIDE], g);
                spart[k * 16 + c] = g;
            }
            __syncthreads();

            // x update for this block's 16 columns (exact scalar formula)
            if (tid < 16) {
                float g = 0.0f;
#pragma unroll
                for (int k = 0; k < 32; k++) g += spart[k * 16 + tid];
                int col = j * NB + tid;
                float xo  = sx[col];
                float den = __fadd_rn(1.0f, __fmul_rn(C_SCALE, g));
                float lr  = __fdiv_rn(C_ALPHA, den);
                float xn  = __fsub_rn(xo, __fmul_rn(lr, g));
                sx[col]   = fmaxf(xn, 0.0f);
            }
            __syncthreads();

            // y pass: y_m += A[m, block] . x'[block]   (next iteration's Ax)
            {
                float acc = 0.0f;
                const float4* row = (const float4*)(sA + tid * STRIDE);
#pragma unroll
                for (int s = 0; s < 4; s++) {
                    float4 a = row[s];
                    int c = j * NB + s * 4;
                    acc = fmaf(a.x, sx[c + 0], acc);
                    acc = fmaf(a.y, sx[c + 1], acc);
                    acc = fmaf(a.z, sx[c + 2], acc);
                    acc = fmaf(a.w, sx[c + 3], acc);
                }
                sy[tid] += acc;
            }
            __syncthreads();   // buffer free
            if (j + 2 < NBLK) load_block(sA, Ap, j + 2, tid);
        }

        // speculatively prefetch blocks 0,1 for the next sweep
        load_block(sA0, Ap, 0, tid);
        load_block(sA1, Ap, 1, tid);

        // finalize
        float vv = fmaxf(__fadd_rn(sy[tid], -sb[tid]), 0.0f);
        sviol[tid] = vv;
#pragma unroll
        for (int o = 16; o > 0; o >>= 1) vv += __shfl_down_sync(0xffffffffu, vv, o);
        if ((tid & 31) == 0) sred[tid >> 5] = vv;
        __syncthreads();
        if (tid < 32) {
            float w = (tid < 16) ? sred[tid] : 0.0f;
#pragma unroll
            for (int o = 8; o > 0; o >>= 1) w += __shfl_down_sync(0xffffffffu, w, o);
            if (tid == 0) sred[16] = w;
        }
        __syncthreads();
        total = sred[16];
        it++;
    }

    cp_wait0();            // drain speculative loads before exit
    xout[p * NN + tid] = sx[tid];
}

extern "C" void kernel_launch(void* const* d_in, const int* in_sizes, int n_in,
                              void* d_out, int out_size) {
    // metadata order: x [B,S,N], A [B,S,M,N], b [B,S,M]
    const float* x = (const float*)d_in[0];
    const float* A = (const float*)d_in[1];
    const float* b = (const float*)d_in[2];
    float* out = (float*)d_out;

    // Defensive: A is the (only) large input.
    if (n_in == 3 && in_sizes[0] > in_sizes[1]) {
        A = (const float*)d_in[0];
        x = (const float*)d_in[1];
    }

    int nprob = out_size / NN;   // 256
    size_t smem_bytes = (size_t)(2 * NN * STRIDE + NN + MM + MM + MM + TPB + 32) * sizeof(float);

    cudaFuncSetAttribute(lva_kernel, cudaFuncAttributeMaxDynamicSharedMemorySize,
                         (int)smem_bytes);
    lva_kernel<<<nprob, TPB, smem_bytes>>>(x, A, b, out);
}

// round 3
// speedup vs baseline: 1.1655x; 1.1655x over previous
#include <cuda_runtime.h>

// Problem constants
#define NN      512
#define MM      512
#define NB      16            // columns per tile
#define NBLK    (NN / NB)     // 32 tiles per problem
#define TILE_F  (MM * NB)     // 8192 floats = 32 KB per tile
#define TPB     512
#define NPROB   256
#define C_ALPHA 0.005f
#define C_SCALE 0.001f
#define C_DELTA 0.1f
#define MAX_UPD 51

// Retiled A: [prob][tile j][512 rows x 16 cols, swizzled], each tile contiguous 32KB.
__device__ float d_At[(size_t)NPROB * NN * MM];

__device__ __forceinline__ void cp_async16(float* dst_smem, const float* src_gmem) {
    unsigned d = (unsigned)__cvta_generic_to_shared(dst_smem);
    asm volatile("cp.async.cg.shared.global [%0], [%1], 16;" :: "r"(d), "l"(src_gmem));
}
__device__ __forceinline__ void cp_commit() { asm volatile("cp.async.commit_group;"); }
__device__ __forceinline__ void cp_wait0()  { asm volatile("cp.async.wait_group 0;"); }
__device__ __forceinline__ void cp_wait2()  { asm volatile("cp.async.wait_group 2;"); }

// ---------------- retile kernel: A row-major -> contiguous swizzled tiles ----------------
// Swizzle: logical (row r, tile-col c) stored at r*16 + ((c>>2) ^ ((r>>1)&3))*4 + (c&3).
__global__ __launch_bounds__(TPB)
void retile_kernel(const float* __restrict__ Ain) {
    const int p   = blockIdx.x;
    const int tid = threadIdx.x;
    const float* Ap = Ain + (size_t)p * (MM * NN);
    float* Tp = d_At + (size_t)p * (MM * NN);

#pragma unroll 4
    for (int i = 0; i < (MM * NN / 4) / TPB; i++) {   // 128 float4 per thread
        int lin = i * TPB + tid;                      // float4 index 0..65535
        int r    = lin >> 7;                          // row 0..511
        int rest = lin & 127;                         // float4 within row
        int j    = rest >> 2;                         // tile 0..31
        int s    = rest & 3;                          // logical segment
        float4 v = *(const float4*)(Ap + (size_t)r * NN + rest * 4);
        int phys = s ^ ((r >> 1) & 3);
        *(float4*)(Tp + (size_t)j * TILE_F + r * NB + phys * 4) = v;
    }
}

// ---------------- main kernel ----------------
extern __shared__ float smem[];

__device__ __forceinline__ void load_tile(float* dst, const float* __restrict__ src, int tid) {
#pragma unroll
    for (int i = 0; i < 4; i++) {
        int lin = i * TPB + tid;          // 0..2047 float4s
        cp_async16(dst + lin * 4, src + lin * 4);
    }
    cp_commit();
}

__global__ __launch_bounds__(TPB, 2)
void lva_kernel(const float* __restrict__ xin,
                const float* __restrict__ bin,
                float* __restrict__ xout) {
    const int p   = blockIdx.x;
    const int tid = threadIdx.x;

    float* sA[3];
    sA[0] = smem;
    sA[1] = sA[0] + TILE_F;
    sA[2] = sA[1] + TILE_F;
    float* sx    = sA[2] + TILE_F;   // 512
    float* sy    = sx + NN;          // 512
    float* sviol = sy + MM;          // 512
    float* sb    = sviol + MM;       // 512
    float* spart = sb + MM;          // 512
    float* sred  = spart + TPB;      // 32

    const float* Tp = d_At + (size_t)p * (MM * NN);

    sx[tid] = xin[p * NN + tid];
    sb[tid] = bin[p * MM + tid];
    sy[tid] = 0.0f;
    __syncthreads();

    // rolling load pipeline: global counter gc; buffer = gc % 3, block = gc & 31
    unsigned gc = 0;                 // next tile to consume
    load_tile(sA[0], Tp + 0 * TILE_F, tid);
    load_tile(sA[1], Tp + 1 * TILE_F, tid);
    load_tile(sA[2], Tp + 2 * TILE_F, tid);
    unsigned gl = 3;                 // next tile to issue

    const int q = (tid >> 1) & 3;    // per-row swizzle key for y-pass

    // ---------- initial sweep: y = A @ x ----------
    for (int j = 0; j < NBLK; j++) {
        cp_wait2();
        __syncthreads();
        const float* A = sA[gc % 3];

        float acc = 0.0f;
        const float4* row = (const float4*)(A + tid * NB);
#pragma unroll
        for (int s = 0; s < 4; s++) {
            float4 a = row[s ^ q];           // physical segment (de-swizzle)
            int c = j * NB + s * 4;          // logical columns (warp-uniform)
            acc = fmaf(a.x, sx[c + 0], acc);
            acc = fmaf(a.y, sx[c + 1], acc);
            acc = fmaf(a.z, sx[c + 2], acc);
            acc = fmaf(a.w, sx[c + 3], acc);
        }
        sy[tid] += acc;
        __syncthreads();                     // buffer free
        load_tile(sA[gl % 3], Tp + (size_t)(gl & 31) * TILE_F, tid);
        gl++; gc++;
    }

    // ---------- finalize: viol, total ----------
    float v = fmaxf(__fadd_rn(sy[tid], -sb[tid]), 0.0f);
    sviol[tid] = v;
#pragma unroll
    for (int o = 16; o > 0; o >>= 1) v += __shfl_down_sync(0xffffffffu, v, o);
    if ((tid & 31) == 0) sred[tid >> 5] = v;
    __syncthreads();
    if (tid < 32) {
        float w = (tid < 16) ? sred[tid] : 0.0f;
#pragma unroll
        for (int o = 8; o > 0; o >>= 1) w += __shfl_down_sync(0xffffffffu, w, o);
        if (tid == 0) sred[16] = w;
    }
    __syncthreads();
    float total = sred[16];

    // g-pass constants: thread handles logical column c, row set {k + 32*i}
    const int gc_c = tid & 15;
    const int gc_k = tid >> 4;                       // 0..31
    const int gc_off = gc_k * NB + ((gc_c >> 2) ^ ((gc_k >> 1) & 3)) * 4 + (gc_c & 3);

    // ---------- iterate ----------
    int it = 0;
    while (it < MAX_UPD && total >= C_DELTA) {
        sy[tid] = 0.0f;

        for (int j = 0; j < NBLK; j++) {
            cp_wait2();
            __syncthreads();
            const float* A = sA[gc % 3];

            // g pass: g_c = sum_m viol[m] * A[m, c]; rows m = k + 32*i
            {
                const float* ap = A + gc_off;        // stride 32*16 = 512 floats
                const float* vp = sviol + gc_k;      // stride 32
                float g = 0.0f;
#pragma unroll
                for (int i = 0; i < 16; i++)
                    g = fmaf(vp[i * 32], ap[i * 512], g);
                spart[gc_k * NB + gc_c] = g;
            }
            __syncthreads();

            // x update for this block's 16 columns (exact scalar formula)
            if (tid < NB) {
                float g = 0.0f;
#pragma unroll
                for (int k = 0; k < 32; k++) g += spart[k * NB + tid];
                int col = j * NB + tid;
                float xo  = sx[col];
                float den = __fadd_rn(1.0f, __fmul_rn(C_SCALE, g));
                float lr  = __fdiv_rn(C_ALPHA, den);
                float xn  = __fsub_rn(xo, __fmul_rn(lr, g));
                sx[col]   = fmaxf(xn, 0.0f);
            }
            __syncthreads();

            // y pass: y_m += A[m, block] . x'[block]
            {
                float acc = 0.0f;
                const float4* row = (const float4*)(A + tid * NB);
#pragma unroll
                for (int s = 0; s < 4; s++) {
                    float4 a = row[s ^ q];
                    int c = j * NB + s * 4;
                    acc = fmaf(a.x, sx[c + 0], acc);
                    acc = fmaf(a.y, sx[c + 1], acc);
                    acc = fmaf(a.z, sx[c + 2], acc);
                    acc = fmaf(a.w, sx[c + 3], acc);
                }
                sy[tid] += acc;
            }
            __syncthreads();                 // buffer free
            load_tile(sA[gl % 3], Tp + (size_t)(gl & 31) * TILE_F, tid);
            gl++; gc++;
        }

        // finalize
        float vv = fmaxf(__fadd_rn(sy[tid], -sb[tid]), 0.0f);
        sviol[tid] = vv;
#pragma unroll
        for (int o = 16; o > 0; o >>= 1) vv += __shfl_down_sync(0xffffffffu, vv, o);
        if ((tid & 31) == 0) sred[tid >> 5] = vv;
        __syncthreads();
        if (tid < 32) {
            float w = (tid < 16) ? sred[tid] : 0.0f;
#pragma unroll
            for (int o = 8; o > 0; o >>= 1) w += __shfl_down_sync(0xffffffffu, w, o);
            if (tid == 0) sred[16] = w;
        }
        __syncthreads();
        total = sred[16];
        it++;
    }

    cp_wait0();   // drain speculative loads
    xout[p * NN + tid] = sx[tid];
}

extern "C" void kernel_launch(void* const* d_in, const int* in_sizes, int n_in,
                              void* d_out, int out_size) {
    // metadata order: x [B,S,N], A [B,S,M,N], b [B,S,M]
    const float* x = (const float*)d_in[0];
    const float* A = (const float*)d_in[1];
    const float* b = (const float*)d_in[2];
    float* out = (float*)d_out;

    if (n_in == 3 && in_sizes[0] > in_sizes[1]) {   // defensive: A is the big one
        A = (const float*)d_in[0];
        x = (const float*)d_in[1];
    }

    int nprob = out_size / NN;   // 256

    retile_kernel<<<nprob, TPB>>>(A);

    size_t smem_bytes = (size_t)(3 * TILE_F + NN + MM + MM + MM + TPB + 32) * sizeof(float);
    cudaFuncSetAttribute(lva_kernel, cudaFuncAttributeMaxDynamicSharedMemorySize,
                         (int)smem_bytes);
    lva_kernel<<<nprob, TPB, smem_bytes>>>(x, b, out);
}

// round 4
// speedup vs baseline: 1.5363x; 1.3181x over previous
#include <cuda_runtime.h>

#define NN      512
#define MM      512
#define NB      16
#define NBLK    32
#define TILE_F  (MM * NB)      // 8192 floats = 32 KB
#define TPB     512
#define NPROB   256
#define C_ALPHA 0.005f
#define C_SCALE 0.001f
#define C_DELTA 0.1f
#define MAX_UPD 51

// Retiled A: [prob][tile j][512 rows x 16 cols, swizzled], each tile contiguous 32KB.
__device__ float d_At[(size_t)NPROB * NN * MM];

__device__ __forceinline__ void cp_async16(float* dst_smem, const float* src_gmem) {
    unsigned d = (unsigned)__cvta_generic_to_shared(dst_smem);
    asm volatile("cp.async.cg.shared.global [%0], [%1], 16;" :: "r"(d), "l"(src_gmem));
}
__device__ __forceinline__ void cp_commit() { asm volatile("cp.async.commit_group;"); }
__device__ __forceinline__ void cp_wait0()  { asm volatile("cp.async.wait_group 0;"); }
__device__ __forceinline__ void cp_wait1()  { asm volatile("cp.async.wait_group 1;"); }

// ---------------- retile: A row-major -> contiguous swizzled 32KB tiles ----------------
// logical (row r, tile-col c) -> r*16 + ((c>>2) ^ ((r>>1)&3))*4 + (c&3)
__global__ __launch_bounds__(TPB)
void retile_kernel(const float* __restrict__ Ain) {
    const int p   = blockIdx.x;
    const int tid = threadIdx.x;
    const float* Ap = Ain + (size_t)p * (MM * NN);
    float* Tp = d_At + (size_t)p * (MM * NN);

#pragma unroll 4
    for (int i = 0; i < (MM * NN / 4) / TPB; i++) {
        int lin  = i * TPB + tid;
        int r    = lin >> 7;
        int rest = lin & 127;
        int j    = rest >> 2;
        int s    = rest & 3;
        float4 v = *(const float4*)(Ap + (size_t)r * NN + rest * 4);
        int phys = s ^ ((r >> 1) & 3);
        *(float4*)(Tp + (size_t)j * TILE_F + r * NB + phys * 4) = v;
    }
}

// ---------------- main kernel ----------------
extern __shared__ float smem[];

__device__ __forceinline__ void load_tile(float* dst, const float* __restrict__ src, int tid) {
#pragma unroll
    for (int i = 0; i < 4; i++) {
        int lin = i * TPB + tid;
        cp_async16(dst + lin * 4, src + lin * 4);
    }
    cp_commit();
}

__global__ __launch_bounds__(TPB, 2)
void lva_kernel(const float* __restrict__ xin,
                const float* __restrict__ bin,
                float* __restrict__ xout) {
    const int p   = blockIdx.x;
    const int tid = threadIdx.x;

    float* sA[3];
    sA[0] = smem;
    sA[1] = sA[0] + TILE_F;
    sA[2] = sA[1] + TILE_F;
    float* sx    = sA[2] + TILE_F;   // 512
    float* sviol = sx + NN;          // 512
    float* spart = sviol + MM;       // 512
    float* sxblk = spart + TPB;      // 16
    float* sred  = sxblk + 16;       // 32

    const float* Tp = d_At + (size_t)p * (MM * NN);

    sx[tid] = xin[p * NN + tid];
    const float breg = bin[p * MM + tid];
    __syncthreads();

    load_tile(sA[0], Tp, tid);
    load_tile(sA[1], Tp + TILE_F, tid);
    unsigned gl = 2;        // next tile index to issue (mod 32 within A)
    unsigned gcnt = 0;      // tiles consumed (buffer = gcnt % 3)

    const int q    = (tid >> 1) & 3;          // y-pass swizzle key
    const int col  = tid & 15;                // g-pass column
    const int krow = tid >> 4;                // g-pass row phase (0..31)
    const int goff = krow * NB + (((col >> 2) ^ ((krow >> 1) & 3)) << 2) + (col & 3);

    float vr[16];           // viol values for g-pass (rows krow + 32i)
    float yacc = 0.0f;

    // ---------- initial sweep: y = A @ x ----------
    for (int j = 0; j < NBLK; j++) {
        cp_wait1();
        __syncthreads();
        load_tile(sA[gl % 3], Tp + (size_t)(gl & 31) * TILE_F, tid); gl++;
        const float* A = sA[gcnt % 3]; gcnt++;

        const float4* xq = (const float4*)(sx + j * NB);
        float4 x0 = xq[0], x1 = xq[1], x2 = xq[2], x3 = xq[3];
        const float4* row = (const float4*)(A + tid * NB);
        float4 a0 = row[0 ^ q], a1 = row[1 ^ q], a2 = row[2 ^ q], a3 = row[3 ^ q];

        yacc = fmaf(a0.x, x0.x, yacc); yacc = fmaf(a0.y, x0.y, yacc);
        yacc = fmaf(a0.z, x0.z, yacc); yacc = fmaf(a0.w, x0.w, yacc);
        yacc = fmaf(a1.x, x1.x, yacc); yacc = fmaf(a1.y, x1.y, yacc);
        yacc = fmaf(a1.z, x1.z, yacc); yacc = fmaf(a1.w, x1.w, yacc);
        yacc = fmaf(a2.x, x2.x, yacc); yacc = fmaf(a2.y, x2.y, yacc);
        yacc = fmaf(a2.z, x2.z, yacc); yacc = fmaf(a2.w, x2.w, yacc);
        yacc = fmaf(a3.x, x3.x, yacc); yacc = fmaf(a3.y, x3.y, yacc);
        yacc = fmaf(a3.z, x3.z, yacc); yacc = fmaf(a3.w, x3.w, yacc);
    }

    // ---------- finalize: viol, total, preload viol regs ----------
    float total;
    {
        float v = fmaxf(__fadd_rn(yacc, -breg), 0.0f);
        sviol[tid] = v;
        float t = v;
#pragma unroll
        for (int o = 16; o > 0; o >>= 1) t += __shfl_down_sync(0xffffffffu, t, o);
        if ((tid & 31) == 0) sred[tid >> 5] = t;
        __syncthreads();
        if (tid < 32) {
            float w = (tid < 16) ? sred[tid] : 0.0f;
#pragma unroll
            for (int o = 8; o > 0; o >>= 1) w += __shfl_down_sync(0xffffffffu, w, o);
            if (tid == 0) sred[16] = w;
        }
        __syncthreads();
        total = sred[16];
#pragma unroll
        for (int i = 0; i < 16; i++) vr[i] = sviol[krow + 32 * i];
        yacc = 0.0f;
    }

    // ---------- iterate ----------
    int it = 0;
    while (it < MAX_UPD && total >= C_DELTA) {
        for (int j = 0; j < NBLK; j++) {
            cp_wait1();
            __syncthreads();
            load_tile(sA[gl % 3], Tp + (size_t)(gl & 31) * TILE_F, tid); gl++;
            const float* A = sA[gcnt % 3]; gcnt++;

            // g pass: g_c = sum_i vr[i] * A[krow+32i, c]
            {
                const float* ap = A + goff;          // stride 512 floats per i
                float g = 0.0f;
#pragma unroll
                for (int i = 0; i < 16; i++)
                    g = fmaf(vr[i], ap[i * 512], g);
                spart[krow * NB + col] = g;
            }
            __syncthreads();

            // x update for this block's 16 columns (exact scalar formula)
            if (tid < NB) {
                float g = 0.0f;
#pragma unroll
                for (int k = 0; k < 32; k++) g += spart[k * NB + tid];
                float xo  = sx[j * NB + tid];
                float den = __fadd_rn(1.0f, __fmul_rn(C_SCALE, g));
                float lr  = __fdiv_rn(C_ALPHA, den);
                float xn  = fmaxf(__fsub_rn(xo, __fmul_rn(lr, g)), 0.0f);
                sx[j * NB + tid] = xn;
                sxblk[tid] = xn;
            }
            __syncthreads();

            // y pass: yacc += A[tid, block] . x'[block]
            {
                const float4* xq = (const float4*)sxblk;
                float4 x0 = xq[0], x1 = xq[1], x2 = xq[2], x3 = xq[3];
                const float4* row = (const float4*)(A + tid * NB);
                float4 a0 = row[0 ^ q], a1 = row[1 ^ q], a2 = row[2 ^ q], a3 = row[3 ^ q];

                yacc = fmaf(a0.x, x0.x, yacc); yacc = fmaf(a0.y, x0.y, yacc);
                yacc = fmaf(a0.z, x0.z, yacc); yacc = fmaf(a0.w, x0.w, yacc);
                yacc = fmaf(a1.x, x1.x, yacc); yacc = fmaf(a1.y, x1.y, yacc);
                yacc = fmaf(a1.z, x1.z, yacc); yacc = fmaf(a1.w, x1.w, yacc);
                yacc = fmaf(a2.x, x2.x, yacc); yacc = fmaf(a2.y, x2.y, yacc);
                yacc = fmaf(a2.z, x2.z, yacc); yacc = fmaf(a2.w, x2.w, yacc);
                yacc = fmaf(a3.x, x3.x, yacc); yacc = fmaf(a3.y, x3.y, yacc);
                yacc = fmaf(a3.z, x3.z, yacc); yacc = fmaf(a3.w, x3.w, yacc);
            }
        }

        // finalize: viol, total, reload viol regs
        {
            float v = fmaxf(__fadd_rn(yacc, -breg), 0.0f);
            sviol[tid] = v;
            float t = v;
#pragma unroll
            for (int o = 16; o > 0; o >>= 1) t += __shfl_down_sync(0xffffffffu, t, o);
            if ((tid & 31) == 0) sred[tid >> 5] = t;
            __syncthreads();
            if (tid < 32) {
                float w = (tid < 16) ? sred[tid] : 0.0f;
#pragma unroll
                for (int o = 8; o > 0; o >>= 1) w += __shfl_down_sync(0xffffffffu, w, o);
                if (tid == 0) sred[16] = w;
            }
            __syncthreads();
            total = sred[16];
#pragma unroll
            for (int i = 0; i < 16; i++) vr[i] = sviol[krow + 32 * i];
            yacc = 0.0f;
        }
        it++;
    }

    cp_wait0();   // drain outstanding speculative loads
    xout[p * NN + tid] = sx[tid];
}

extern "C" void kernel_launch(void* const* d_in, const int* in_sizes, int n_in,
                              void* d_out, int out_size) {
    // metadata order: x [B,S,N], A [B,S,M,N], b [B,S,M]
    const float* x = (const float*)d_in[0];
    const float* A = (const float*)d_in[1];
    const float* b = (const float*)d_in[2];
    float* out = (float*)d_out;

    if (n_in == 3 && in_sizes[0] > in_sizes[1]) {   // defensive: A is the big one
        A = (const float*)d_in[0];
        x = (const float*)d_in[1];
    }

    int nprob = out_size / NN;   // 256

    retile_kernel<<<nprob, TPB>>>(A);

    size_t smem_bytes = (size_t)(3 * TILE_F + NN + MM + TPB + 16 + 32) * sizeof(float);
    cudaFuncSetAttribute(lva_kernel, cudaFuncAttributeMaxDynamicSharedMemorySize,
                         (int)smem_bytes);
    lva_kernel<<<nprob, TPB, smem_bytes>>>(x, b, out);
}

// round 5
// speedup vs baseline: 1.9577x; 1.2743x over previous
#include <cuda_runtime.h>
#include <cuda_fp16.h>

#define NN      512
#define MM      512
#define NB      16
#define NBLK    32
#define TILE_H  (MM * NB)      // 8192 halves = 16 KB per tile
#define TPB     512
#define NPROB   256
#define C_ALPHA 0.005f
#define C_SCALE 0.001f
#define C_DELTA 0.1f
#define MAX_UPD 51

// Retiled A (fp16): [prob][tile j][512 rows x 16 cols, swizzled], contiguous 16KB tiles.
// Swizzle: row r has two 16B segments; logical seg s stored at phys = s ^ ((r>>2)&1).
__device__ __half d_At[(size_t)NPROB * NN * MM];

__device__ __forceinline__ void cp_async16(void* dst_smem, const void* src_gmem) {
    unsigned d = (unsigned)__cvta_generic_to_shared(dst_smem);
    asm volatile("cp.async.cg.shared.global [%0], [%1], 16;" :: "r"(d), "l"(src_gmem));
}
__device__ __forceinline__ void cp_commit() { asm volatile("cp.async.commit_group;"); }
__device__ __forceinline__ void cp_wait0()  { asm volatile("cp.async.wait_group 0;"); }
__device__ __forceinline__ void cp_wait2()  { asm volatile("cp.async.wait_group 2;"); }

// ---------------- retile + quantize: fp32 row-major -> fp16 swizzled 16KB tiles ----------
__global__ __launch_bounds__(TPB)
void retile_kernel(const float* __restrict__ Ain) {
    const int p   = blockIdx.x;
    const int tid = threadIdx.x;
    const float* Ap = Ain + (size_t)p * (MM * NN);
    __half* Tp = d_At + (size_t)p * (MM * NN);

    __shared__ __half st[32 * 512];   // 32 rows staged, tile-grouped: j*512 + r'*16 + phys*8

    for (int rb = 0; rb < 16; rb++) {            // 32-row groups
        // Phase A: coalesced fp32 row reads -> fp16 swizzled smem
#pragma unroll
        for (int i = 0; i < 4; i++) {
            int lin  = i * TPB + tid;            // 0..2047 (16B units)
            int rr   = lin >> 6;                 // row within group
            int unit = lin & 63;
            int j    = unit >> 1;                // tile
            int s    = unit & 1;                 // logical segment
            int r    = rb * 32 + rr;
            const float4* src = (const float4*)(Ap + (size_t)r * NN + j * 16 + s * 8);
            float4 a = src[0], b = src[1];
            int phys = s ^ ((r >> 2) & 1);
            __half2* d = (__half2*)(st + j * 512 + rr * 16 + phys * 8);
            d[0] = __floats2half2_rn(a.x, a.y);
            d[1] = __floats2half2_rn(a.z, a.w);
            d[2] = __floats2half2_rn(b.x, b.y);
            d[3] = __floats2half2_rn(b.z, b.w);
        }
        __syncthreads();
        // Phase B: contiguous 1KB-per-tile chunk writes
#pragma unroll
        for (int i = 0; i < 4; i++) {
            int dlin = i * TPB + tid;            // 0..2047
            int j = dlin >> 6;
            int u = dlin & 63;
            uint4 v = ((const uint4*)(st + j * 512))[u];
            ((uint4*)(Tp + (size_t)j * TILE_H + rb * 512))[u] = v;
        }
        __syncthreads();
    }
}

// ---------------- main kernel ----------------
extern __shared__ __half smh[];

__device__ __forceinline__ void load_tile(__half* dst, const __half* __restrict__ src, int tid) {
#pragma unroll
    for (int i = 0; i < 2; i++) {
        int lin = i * TPB + tid;                 // 0..1023 (16B units)
        cp_async16(dst + lin * 8, src + lin * 8);
    }
    cp_commit();
}

#define ACCP(u, xv0, xv1) { __half2 _h = *(__half2*)&(u); float2 _f = __half22float2(_h); \
                            yacc = fmaf(_f.x, (xv0), yacc); yacc = fmaf(_f.y, (xv1), yacc); }

__global__ __launch_bounds__(TPB, 2)
void lva_kernel(const float* __restrict__ xin,
                const float* __restrict__ bin,
                float* __restrict__ xout) {
    const int p   = blockIdx.x;
    const int tid = threadIdx.x;

    __half* sA[4];
    sA[0] = smh;
    sA[1] = sA[0] + TILE_H;
    sA[2] = sA[1] + TILE_H;
    sA[3] = sA[2] + TILE_H;
    float* sx    = (float*)(sA[3] + TILE_H);   // 512
    float* sviol = sx + NN;                    // 512
    float* spart = sviol + MM;                 // 512
    float* sxblk = spart + TPB;                // 16
    float* sred  = sxblk + 16;                 // 32

    const __half* Tp = d_At + (size_t)p * (MM * NN);

    sx[tid] = xin[p * NN + tid];
    const float breg = bin[p * MM + tid];
    __syncthreads();

    load_tile(sA[0], Tp, tid);
    load_tile(sA[1], Tp + TILE_H, tid);
    load_tile(sA[2], Tp + 2 * TILE_H, tid);
    unsigned gl = 3;       // next tile to issue
    unsigned gcnt = 0;     // tiles consumed (buffer = gcnt & 3)

    const int q    = (tid >> 2) & 1;          // y-pass swizzle key (row = tid)
    const int col  = tid & 15;                // g-pass column
    const int krow = tid >> 4;                // g-pass row phase (0..31)
    const int goff = krow * 16 + (((col >> 3) ^ ((krow >> 2) & 1)) << 3) + (col & 7);

    float vr[16];
    float yacc = 0.0f;

    // ---------- initial sweep: y = A @ x ----------
    for (int j = 0; j < NBLK; j++) {
        cp_wait2();
        __syncthreads();
        load_tile(sA[gl & 3], Tp + (size_t)(gl & 31) * TILE_H, tid); gl++;
        const __half* A = sA[gcnt & 3]; gcnt++;

        const float4* xq = (const float4*)(sx + j * NB);
        float4 x0 = xq[0], x1 = xq[1], x2 = xq[2], x3 = xq[3];
        const uint4* rowp = (const uint4*)(A + tid * 16);
        uint4 c0 = rowp[q];        // logical seg 0 (cols 0..7)
        uint4 c1 = rowp[q ^ 1];    // logical seg 1 (cols 8..15)

        ACCP(c0.x, x0.x, x0.y); ACCP(c0.y, x0.z, x0.w);
        ACCP(c0.z, x1.x, x1.y); ACCP(c0.w, x1.z, x1.w);
        ACCP(c1.x, x2.x, x2.y); ACCP(c1.y, x2.z, x2.w);
        ACCP(c1.z, x3.x, x3.y); ACCP(c1.w, x3.z, x3.w);
    }

    // ---------- finalize ----------
    float total;
    {
        float v = fmaxf(__fadd_rn(yacc, -breg), 0.0f);
        sviol[tid] = v;
        float t = v;
#pragma unroll
        for (int o = 16; o > 0; o >>= 1) t += __shfl_down_sync(0xffffffffu, t, o);
        if ((tid & 31) == 0) sred[tid >> 5] = t;
        __syncthreads();
        if (tid < 32) {
            float w = (tid < 16) ? sred[tid] : 0.0f;
#pragma unroll
            for (int o = 8; o > 0; o >>= 1) w += __shfl_down_sync(0xffffffffu, w, o);
            if (tid == 0) sred[16] = w;
        }
        __syncthreads();
        total = sred[16];
#pragma unroll
        for (int i = 0; i < 16; i++) vr[i] = sviol[krow + 32 * i];
        yacc = 0.0f;
    }

    // ---------- iterate ----------
    int it = 0;
    while (it < MAX_UPD && total >= C_DELTA) {
        for (int j = 0; j < NBLK; j++) {
            cp_wait2();
            __syncthreads();
            load_tile(sA[gl & 3], Tp + (size_t)(gl & 31) * TILE_H, tid); gl++;
            const __half* A = sA[gcnt & 3]; gcnt++;

            // g pass: g_c = sum_i vr[i] * A[krow+32i, c]
            {
                const __half* ap = A + goff;         // stride 512 halves per i
                float g = 0.0f;
#pragma unroll
                for (int i = 0; i < 16; i++)
                    g = fmaf(vr[i], __half2float(ap[i * 512]), g);
                spart[krow * NB + col] = g;
            }
            __syncthreads();

            // x update for this block's 16 columns (exact fp32 scalar formula)
            if (tid < NB) {
                float g = 0.0f;
#pragma unroll
                for (int k = 0; k < 32; k++) g += spart[k * NB + tid];
                float xo  = sx[j * NB + tid];
                float den = __fadd_rn(1.0f, __fmul_rn(C_SCALE, g));
                float lr  = __fdiv_rn(C_ALPHA, den);
                float xn  = fmaxf(__fsub_rn(xo, __fmul_rn(lr, g)), 0.0f);
                sx[j * NB + tid] = xn;
                sxblk[tid] = xn;
            }
            __syncthreads();

            // y pass: yacc += A[tid, block] . x'[block]
            {
                const float4* xq = (const float4*)sxblk;
                float4 x0 = xq[0], x1 = xq[1], x2 = xq[2], x3 = xq[3];
                const uint4* rowp = (const uint4*)(A + tid * 16);
                uint4 c0 = rowp[q];
                uint4 c1 = rowp[q ^ 1];

                ACCP(c0.x, x0.x, x0.y); ACCP(c0.y, x0.z, x0.w);
                ACCP(c0.z, x1.x, x1.y); ACCP(c0.w, x1.z, x1.w);
                ACCP(c1.x, x2.x, x2.y); ACCP(c1.y, x2.z, x2.w);
                ACCP(c1.z, x3.x, x3.y); ACCP(c1.w, x3.z, x3.w);
            }
        }

        // finalize
        {
            float v = fmaxf(__fadd_rn(yacc, -breg), 0.0f);
            sviol[tid] = v;
            float t = v;
#pragma unroll
            for (int o = 16; o > 0; o >>= 1) t += __shfl_down_sync(0xffffffffu, t, o);
            if ((tid & 31) == 0) sred[tid >> 5] = t;
            __syncthreads();
            if (tid < 32) {
                float w = (tid < 16) ? sred[tid] : 0.0f;
#pragma unroll
                for (int o = 8; o > 0; o >>= 1) w += __shfl_down_sync(0xffffffffu, w, o);
                if (tid == 0) sred[16] = w;
            }
            __syncthreads();
            total = sred[16];
#pragma unroll
            for (int i = 0; i < 16; i++) vr[i] = sviol[krow + 32 * i];
            yacc = 0.0f;
        }
        it++;
    }

    cp_wait0();   // drain outstanding speculative loads
    xout[p * NN + tid] = sx[tid];
}

extern "C" void kernel_launch(void* const* d_in, const int* in_sizes, int n_in,
                              void* d_out, int out_size) {
    // metadata order: x [B,S,N], A [B,S,M,N], b [B,S,M]
    const float* x = (const float*)d_in[0];
    const float* A = (const float*)d_in[1];
    const float* b = (const float*)d_in[2];
    float* out = (float*)d_out;

    if (n_in == 3 && in_sizes[0] > in_sizes[1]) {   // defensive: A is the big one
        A = (const float*)d_in[0];
        x = (const float*)d_in[1];
    }

    int nprob = out_size / NN;   // 256

    retile_kernel<<<nprob, TPB>>>(A);

    size_t smem_bytes = (size_t)(4 * TILE_H) * sizeof(__half)
                      + (size_t)(NN + MM + TPB + 16 + 32) * sizeof(float);
    cudaFuncSetAttribute(lva_kernel, cudaFuncAttributeMaxDynamicSharedMemorySize,
                         (int)smem_bytes);
    lva_kernel<<<nprob, TPB, smem_bytes>>>(x, b, out);
}

// round 6
// speedup vs baseline: 2.6120x; 1.3342x over previous
#include <cuda_runtime.h>
#include <cuda_fp16.h>

#define NN      512
#define MM      512
#define NB      32
#define NBLK    16
#define TILE_H  (MM * NB)      // 16384 halves = 32 KB per tile
#define TPB     512
#define NPROB   256
#define C_ALPHA 0.005f
#define C_SCALE 0.001f
#define C_DELTA 0.1f
#define MAX_UPD 51

// Retiled A (fp16): [prob][tile j][512 rows x 32 cols], row=64B=4 segs of 16B,
// swizzle: logical seg s stored at phys = s ^ ((r>>1)&3).
__device__ __half d_At[(size_t)NPROB * NN * MM];

__device__ __forceinline__ void cp_async16(void* dst_smem, const void* src_gmem) {
    unsigned d = (unsigned)__cvta_generic_to_shared(dst_smem);
    asm volatile("cp.async.cg.shared.global [%0], [%1], 16;" :: "r"(d), "l"(src_gmem));
}
__device__ __forceinline__ void cp_commit() { asm volatile("cp.async.commit_group;"); }
__device__ __forceinline__ void cp_wait0()  { asm volatile("cp.async.wait_group 0;"); }
__device__ __forceinline__ void cp_wait1()  { asm volatile("cp.async.wait_group 1;"); }

// ---------------- retile + quantize: fp32 row-major -> fp16 swizzled 32KB tiles ----------
__global__ __launch_bounds__(TPB)
void retile_kernel(const float* __restrict__ Ain) {
    const int p   = blockIdx.x;
    const int tid = threadIdx.x;
    const float* Ap = Ain + (size_t)p * (MM * NN);
    __half* Tp = d_At + (size_t)p * (MM * NN);

    __shared__ __half st[16 * 1024];   // 16 tiles x (32 rows x 32 cols) staged

    for (int rb = 0; rb < 16; rb++) {           // 32-row groups
        // Phase A: coalesced fp32 reads -> fp16 swizzled smem
#pragma unroll
        for (int i = 0; i < 4; i++) {
            int lin  = i * TPB + tid;           // seg id 0..2047
            int rr   = lin >> 6;                // row in group
            int segi = lin & 63;
            int j    = segi >> 2;               // tile 0..15
            int s    = segi & 3;                // logical seg in tile row
            int r    = rb * 32 + rr;
            const float4* src = (const float4*)(Ap + (size_t)r * NN + j * NB + s * 8);
            float4 a = src[0], b = src[1];
            int phys = s ^ ((r >> 1) & 3);
            __half2* d = (__half2*)(st + j * 1024 + rr * NB + phys * 8);
            d[0] = __floats2half2_rn(a.x, a.y);
            d[1] = __floats2half2_rn(a.z, a.w);
            d[2] = __floats2half2_rn(b.x, b.y);
            d[3] = __floats2half2_rn(b.z, b.w);
        }
        __syncthreads();
        // Phase B: contiguous 2KB-per-tile chunk writes
#pragma unroll
        for (int i = 0; i < 4; i++) {
            int dlin = i * TPB + tid;           // 0..2047 16B-units
            int j = dlin >> 7;                  // tile
            int u = dlin & 127;
            uint4 v = ((const uint4*)(st + j * 1024))[u];
            ((uint4*)(Tp + (size_t)j * TILE_H + rb * 1024))[u] = v;
        }
        __syncthreads();
    }
}

// ---------------- main kernel ----------------
extern __shared__ __half smh[];

__device__ __forceinline__ void load_tile(__half* dst, const __half* __restrict__ src, int tid) {
#pragma unroll
    for (int i = 0; i < 4; i++) {
        int lin = i * TPB + tid;                // 0..2047 16B-units
        cp_async16(dst + lin * 8, src + lin * 8);
    }
    cp_commit();
}

#define ACCP(u, xv0, xv1) { __half2 _h = *(__half2*)&(u); float2 _f = __half22float2(_h); \
                            yacc = fmaf(_f.x, (xv0), yacc); yacc = fmaf(_f.y, (xv1), yacc); }

#define YSEG(cs, xa, xb) { ACCP((cs).x, (xa).x, (xa).y); ACCP((cs).y, (xa).z, (xa).w); \
                           ACCP((cs).z, (xb).x, (xb).y); ACCP((cs).w, (xb).z, (xb).w); }

__global__ __launch_bounds__(TPB, 2)
void lva_kernel(const float* __restrict__ xin,
                const float* __restrict__ bin,
                float* __restrict__ xout) {
    const int p   = blockIdx.x;
    const int tid = threadIdx.x;

    __half* sA[3];
    sA[0] = smh;
    sA[1] = sA[0] + TILE_H;
    sA[2] = sA[1] + TILE_H;
    float* sx    = (float*)(sA[2] + TILE_H);   // 512
    float* sviol = sx + NN;                    // 512
    float* spart = sviol + MM;                 // 1024 ([32 phases][32 cols])
    float* sxblk = spart + 1024;               // 32
    float* sred  = sxblk + 32;                 // 32

    const __half* Tp = d_At + (size_t)p * (MM * NN);

    sx[tid] = xin[p * NN + tid];
    const float breg = bin[p * MM + tid];
    __syncthreads();

    load_tile(sA[0], Tp, tid);
    load_tile(sA[1], Tp + TILE_H, tid);
    unsigned gl = 2;       // next tile to issue (buffer gl%3, tile gl&15)
    unsigned gcnt = 0;     // tiles consumed

    const int q2   = (tid >> 1) & 3;          // y-pass swizzle key (row = tid)
    const int c2   = tid & 15;                // g-pass column pair (cols 2c2, 2c2+1)
    const int krow = tid >> 4;                // g-pass row phase (0..31)
    // halves offset: row krow, colpair c2, swizzled ((krow>>1)&3 invariant under +32i)
    const int goff = krow * NB + (((c2 >> 2) ^ ((krow >> 1) & 3)) << 3) + ((c2 & 3) << 1);

    float vr[16];
    float yacc = 0.0f;

    // ---------- initial sweep: y = A @ x ----------
    for (int j = 0; j < NBLK; j++) {
        cp_wait1();
        __syncthreads();
        load_tile(sA[gl % 3], Tp + (size_t)(gl & 15) * TILE_H, tid); gl++;
        const __half* A = sA[gcnt % 3]; gcnt++;

        const float4* xq = (const float4*)(sx + j * NB);
        const uint4* rowp = (const uint4*)(A + tid * NB);
#pragma unroll
        for (int s = 0; s < 4; s++) {
            uint4 cs = rowp[s ^ q2];
            float4 xa = xq[2 * s], xb = xq[2 * s + 1];
            YSEG(cs, xa, xb);
        }
    }

    // ---------- finalize ----------
    float total;
    {
        float v = fmaxf(__fadd_rn(yacc, -breg), 0.0f);
        sviol[tid] = v;
        float t = v;
#pragma unroll
        for (int o = 16; o > 0; o >>= 1) t += __shfl_down_sync(0xffffffffu, t, o);
        if ((tid & 31) == 0) sred[tid >> 5] = t;
        __syncthreads();
        if (tid < 32) {
            float w = (tid < 16) ? sred[tid] : 0.0f;
#pragma unroll
            for (int o = 8; o > 0; o >>= 1) w += __shfl_down_sync(0xffffffffu, w, o);
            if (tid == 0) sred[16] = w;
        }
        __syncthreads();
        total = sred[16];
#pragma unroll
        for (int i = 0; i < 16; i++) vr[i] = sviol[krow + 32 * i];
        yacc = 0.0f;
    }

    // ---------- iterate ----------
    int it = 0;
    while (it < MAX_UPD && total >= C_DELTA) {
        for (int j = 0; j < NBLK; j++) {
            cp_wait1();
            __syncthreads();
            load_tile(sA[gl % 3], Tp + (size_t)(gl & 15) * TILE_H, tid); gl++;
            const __half* A = sA[gcnt % 3]; gcnt++;

            // g pass: colpair (2c2,2c2+1), rows krow+32i
            {
                const __half2* ap = (const __half2*)(A + goff);  // stride 512 half2 per i
                float g0 = 0.0f, g1 = 0.0f;
#pragma unroll
                for (int i = 0; i < 16; i++) {
                    float2 f = __half22float2(ap[i * 512]);
                    g0 = fmaf(vr[i], f.x, g0);
                    g1 = fmaf(vr[i], f.y, g1);
                }
                spart[krow * NB + 2 * c2]     = g0;
                spart[krow * NB + 2 * c2 + 1] = g1;
            }
            __syncthreads();

            // x update for this block's 32 columns (exact fp32 scalar formula)
            if (tid < NB) {
                float g = 0.0f;
#pragma unroll
                for (int k = 0; k < 32; k++) g += spart[k * NB + tid];
                float xo  = sx[j * NB + tid];
                float den = __fadd_rn(1.0f, __fmul_rn(C_SCALE, g));
                float lr  = __fdiv_rn(C_ALPHA, den);
                float xn  = fmaxf(__fsub_rn(xo, __fmul_rn(lr, g)), 0.0f);
                sx[j * NB + tid] = xn;
                sxblk[tid] = xn;
            }
            __syncthreads();

            // y pass: yacc += A[tid, block] . x'[block]
            {
                const float4* xq = (const float4*)sxblk;
                const uint4* rowp = (const uint4*)(A + tid * NB);
#pragma unroll
                for (int s = 0; s < 4; s++) {
                    uint4 cs = rowp[s ^ q2];
                    float4 xa = xq[2 * s], xb = xq[2 * s + 1];
                    YSEG(cs, xa, xb);
                }
            }
        }

        // finalize
        {
            float v = fmaxf(__fadd_rn(yacc, -breg), 0.0f);
            sviol[tid] = v;
            float t = v;
#pragma unroll
            for (int o = 16; o > 0; o >>= 1) t += __shfl_down_sync(0xffffffffu, t, o);
            if ((tid & 31) == 0) sred[tid >> 5] = t;
            __syncthreads();
            if (tid < 32) {
                float w = (tid < 16) ? sred[tid] : 0.0f;
#pragma unroll
                for (int o = 8; o > 0; o >>= 1) w += __shfl_down_sync(0xffffffffu, w, o);
                if (tid == 0) sred[16] = w;
            }
            __syncthreads();
            total = sred[16];
#pragma unroll
            for (int i = 0; i < 16; i++) vr[i] = sviol[krow + 32 * i];
            yacc = 0.0f;
        }
        it++;
    }

    cp_wait0();
    xout[p * NN + tid] = sx[tid];
}

extern "C" void kernel_launch(void* const* d_in, const int* in_sizes, int n_in,
                              void* d_out, int out_size) {
    // metadata order: x [B,S,N], A [B,S,M,N], b [B,S,M]
    const float* x = (const float*)d_in[0];
    const float* A = (const float*)d_in[1];
    const float* b = (const float*)d_in[2];
    float* out = (float*)d_out;

    if (n_in == 3 && in_sizes[0] > in_sizes[1]) {
        A = (const float*)d_in[0];
        x = (const float*)d_in[1];
    }

    int nprob = out_size / NN;   // 256

    retile_kernel<<<nprob, TPB>>>(A);

    size_t smem_bytes = (size_t)(3 * TILE_H) * sizeof(__half)
                      + (size_t)(NN + MM + 1024 + 32 + 32) * sizeof(float);
    cudaFuncSetAttribute(lva_kernel, cudaFuncAttributeMaxDynamicSharedMemorySize,
                         (int)smem_bytes);
    lva_kernel<<<nprob, TPB, smem_bytes>>>(x, b, out);
}